// round 4
// baseline (speedup 1.0000x reference)
#include <cuda_runtime.h>
#include <math.h>

#define T_STEPS 500
#define BATCH   128
#define FDIM    128
#define HDIM    512
#define ODIM    32
#define NSNN    64          // SNN CTAs, 2 batches each

#define GBM 128
#define GBN 128
#define GBK 32

// Scratch (device globals — the sanctioned allocation-free path)
__device__ float g_iin[T_STEPS * BATCH * HDIM];   // 131 MB: x @ W_in^T
__device__ float g_wrecT[HDIM * HDIM];            // W_rec transposed [src][dst]
__device__ float g_woutT[HDIM * ODIM];            // W_out transposed [h][o]
__device__ int   g_cnt[T_STEPS];                  // per-t GEMM tile completion

// ---------------------------------------------------------------------------
// Transpose weights + zero the progress counters (runs first, every replay)
// ---------------------------------------------------------------------------
__global__ void transpose_kernel(const float* __restrict__ W_rec,
                                 const float* __restrict__ W_out) {
    int idx = blockIdx.x * blockDim.x + threadIdx.x;
    if (idx < HDIM * HDIM) {
        int r = idx / HDIM, c = idx % HDIM;
        g_wrecT[c * HDIM + r] = W_rec[idx];
    }
    if (idx < ODIM * HDIM) {
        int o = idx / HDIM, h = idx % HDIM;
        g_woutT[h * ODIM + o] = W_out[idx];
    }
    if (idx < T_STEPS) g_cnt[idx] = 0;
}

// ---------------------------------------------------------------------------
// Fused kernel: bid < NSNN  -> persistent SNN CTA (2 batch elements)
//               bid >= NSNN -> GEMM producer tile (one (t, n-tile) each)
// Shared memory overlaid between the two roles.
// ---------------------------------------------------------------------------
struct SnnSmem {
    float red[2][4][HDIM];   // per-slice partial recurrent sums (A/B)
    int   list[2][HDIM];     // spike lists (A/B)
    int   wcnt[2][16];
};
struct GemmSmem {
    float As[GBK][GBM + 4];
    float Bs[GBK][GBN + 4];
};
union FusedSmem { SnnSmem s; GemmSmem g; };

// sparse gather of one batch's recurrent input (per-slice partial, float4)
__device__ __forceinline__ float4 gather_rec(const int* __restrict__ list, int n,
                                             int slice, const float* __restrict__ wbase) {
    float4 a0 = {0,0,0,0}, a1 = {0,0,0,0}, a2 = {0,0,0,0}, a3 = {0,0,0,0};
    int j = slice;
    for (; j + 12 < n; j += 16) {
        float4 w0 = *(const float4*)(wbase + (size_t)list[j]      * HDIM);
        float4 w1 = *(const float4*)(wbase + (size_t)list[j + 4]  * HDIM);
        float4 w2 = *(const float4*)(wbase + (size_t)list[j + 8]  * HDIM);
        float4 w3 = *(const float4*)(wbase + (size_t)list[j + 12] * HDIM);
        a0.x += w0.x; a0.y += w0.y; a0.z += w0.z; a0.w += w0.w;
        a1.x += w1.x; a1.y += w1.y; a1.z += w1.z; a1.w += w1.w;
        a2.x += w2.x; a2.y += w2.y; a2.z += w2.z; a2.w += w2.w;
        a3.x += w3.x; a3.y += w3.y; a3.z += w3.z; a3.w += w3.w;
    }
    for (; j < n; j += 4) {
        float4 w = *(const float4*)(wbase + (size_t)list[j] * HDIM);
        a0.x += w.x; a0.y += w.y; a0.z += w.z; a0.w += w.w;
    }
    a0.x += a1.x + a2.x + a3.x;
    a0.y += a1.y + a2.y + a3.y;
    a0.z += a1.z + a2.z + a3.z;
    a0.w += a1.w + a2.w + a3.w;
    return a0;
}

__global__ void __launch_bounds__(512) fused_kernel(
    const float* __restrict__ X, const float* __restrict__ Win,
    const float* __restrict__ b_out, float* __restrict__ out) {
    __shared__ FusedSmem sm;
    const int tid = threadIdx.x;

    if (blockIdx.x >= NSNN) {
        // ================== GEMM producer: i_in tile for one timestep ==================
        const int gid = blockIdx.x - NSNN;     // 0..1999
        const int bm  = gid >> 2;              // timestep t (ascending with bid)
        const int bn  = gid & 3;               // n-tile
        const float* Xb = X   + (size_t)bm * GBM * FDIM;
        const float* Wb = Win + (size_t)bn * GBN * FDIM;
        const int ty = tid >> 4;               // 0..31, m-group (4 rows)
        const int tx = tid & 15;               // 0..15, n-group (8 cols)
        const int lrow = tid >> 3;             // 0..63
        const int lcol = (tid & 7) * 4;

        float acc[4][8] = {};
        for (int k0 = 0; k0 < FDIM; k0 += GBK) {
            #pragma unroll
            for (int p = 0; p < 2; p++) {
                int r = lrow + p * 64;
                float4 va = *(const float4*)(Xb + (size_t)r * FDIM + k0 + lcol);
                sm.g.As[lcol + 0][r] = va.x; sm.g.As[lcol + 1][r] = va.y;
                sm.g.As[lcol + 2][r] = va.z; sm.g.As[lcol + 3][r] = va.w;
                float4 vb = *(const float4*)(Wb + (size_t)r * FDIM + k0 + lcol);
                sm.g.Bs[lcol + 0][r] = vb.x; sm.g.Bs[lcol + 1][r] = vb.y;
                sm.g.Bs[lcol + 2][r] = vb.z; sm.g.Bs[lcol + 3][r] = vb.w;
            }
            __syncthreads();
            #pragma unroll
            for (int k = 0; k < GBK; k++) {
                float af[4], bf[8];
                *(float4*)(af)     = *(const float4*)&sm.g.As[k][ty * 4];
                *(float4*)(bf)     = *(const float4*)&sm.g.Bs[k][tx * 8];
                *(float4*)(bf + 4) = *(const float4*)&sm.g.Bs[k][tx * 8 + 4];
                #pragma unroll
                for (int i = 0; i < 4; i++)
                    #pragma unroll
                    for (int j = 0; j < 8; j++)
                        acc[i][j] += af[i] * bf[j];
            }
            __syncthreads();
        }
        float* C = g_iin + (size_t)(bm * GBM) * HDIM + bn * GBN;
        #pragma unroll
        for (int i = 0; i < 4; i++) {
            float4 v0, v1;
            v0.x = acc[i][0]; v0.y = acc[i][1]; v0.z = acc[i][2]; v0.w = acc[i][3];
            v1.x = acc[i][4]; v1.y = acc[i][5]; v1.z = acc[i][6]; v1.w = acc[i][7];
            float* Crow = C + (size_t)(ty * 4 + i) * HDIM + tx * 8;
            *(float4*)(Crow)     = v0;
            *(float4*)(Crow + 4) = v1;
        }
        __threadfence();
        __syncthreads();
        if (tid == 0) atomicAdd(&g_cnt[bm], 1);   // publish: tile done (4 per t)
        return;
    }

    // ================== SNN consumer: 2 batch elements per CTA ==================
    const int bA = blockIdx.x * 2;
    const int bB = bA + 1;
    const int lane  = tid & 31;
    const int warp  = tid >> 5;
    const int slice = tid >> 7;
    const int h4    = tid & 127;

    float vA = 0.f, iA = 0.f, aA = 0.f;
    float vB = 0.f, iB = 0.f, aB = 0.f;
    float oA = 0.f, oB = 0.f;
    float bo = 0.f;
    if (warp < 2) bo = b_out[lane];
    if (tid < 16) { sm.s.wcnt[0][tid] = 0; sm.s.wcnt[1][tid] = 0; }

    const float* iinA = g_iin + (size_t)bA * HDIM + tid;
    const float* iinB = g_iin + (size_t)bB * HDIM + tid;
    float* outA = out + (size_t)bA * ODIM;
    float* outB = out + (size_t)bB * ODIM;
    const float* wbase = g_wrecT + (h4 << 2);

    int nA = 0, nB = 0;

    // wait for i_in[0], acquire
    if (tid == 0) {
        while (*(volatile int*)&g_cnt[0] < 4) __nanosleep(64);
        __threadfence();
    }
    __syncthreads();
    float icA = iinA[0];
    float icB = iinB[0];

    for (int t = 0; t < T_STEPS; t++) {
        // ---- sparse recurrent gathers: A then B (intersection rows hit L1) ----
        float4 gA = gather_rec(sm.s.list[0], nA, slice, wbase);
        *(float4*)&sm.s.red[0][slice][h4 << 2] = gA;
        float4 gB = gather_rec(sm.s.list[1], nB, slice, wbase);
        *(float4*)&sm.s.red[1][slice][h4 << 2] = gB;

        // wait for next step's i_in tiles (producer normally far ahead)
        if (tid == 0 && t + 1 < T_STEPS) {
            while (*(volatile int*)&g_cnt[t + 1] < 4) __nanosleep(64);
            __threadfence();
        }
        __syncthreads();                       // (1) red ready + poll done

        float icA2 = 0.f, icB2 = 0.f;
        if (t + 1 < T_STEPS) {
            icA2 = __ldg(iinA + (size_t)(t + 1) * BATCH * HDIM);
            icB2 = __ldg(iinB + (size_t)(t + 1) * BATCH * HDIM);
        }
        float recA = (sm.s.red[0][0][tid] + sm.s.red[0][1][tid])
                   + (sm.s.red[0][2][tid] + sm.s.red[0][3][tid]);
        float recB = (sm.s.red[1][0][tid] + sm.s.red[1][1][tid])
                   + (sm.s.red[1][2][tid] + sm.s.red[1][3][tid]);

        // ---- LIF-AdEx updates (grouping mirrors the JAX reference) ----
        float dvA    = 0.1f * ((((0.0f - vA) + 0.5f * expf((vA - 1.0f) * 2.0f)) + iA) - aA);
        float vdecA  = vA + dvA;
        float idecA  = iA - 0.2f * iA;
        float adecA  = aA + 0.002f * (4.0f * vA - aA);
        int   zA     = (vdecA - 1.0f) > 0.0f;
        vA = zA ? 0.0f : vdecA;
        iA = (idecA + icA) + recA;
        aA = adecA + (zA ? 0.02f : 0.0f);

        float dvB    = 0.1f * ((((0.0f - vB) + 0.5f * expf((vB - 1.0f) * 2.0f)) + iB) - aB);
        float vdecB  = vB + dvB;
        float idecB  = iB - 0.2f * iB;
        float adecB  = aB + 0.002f * (4.0f * vB - aB);
        int   zB     = (vdecB - 1.0f) > 0.0f;
        vB = zB ? 0.0f : vdecB;
        iB = (idecB + icB) + recB;
        aB = adecB + (zB ? 0.02f : 0.0f);

        // ---- build both spike lists (deterministic ballot-scan compaction) ----
        unsigned balA = __ballot_sync(0xffffffffu, zA);
        unsigned balB = __ballot_sync(0xffffffffu, zB);
        if (lane == 0) {
            sm.s.wcnt[0][warp] = __popc(balA);
            sm.s.wcnt[1][warp] = __popc(balB);
        }
        __syncthreads();                       // (2) counts visible

        int baseA = 0, ntotA = 0, baseB = 0, ntotB = 0;
        #pragma unroll
        for (int w = 0; w < 16; w++) {
            int cA = sm.s.wcnt[0][w], cB = sm.s.wcnt[1][w];
            if (w < warp) { baseA += cA; baseB += cB; }
            ntotA += cA; ntotB += cB;
        }
        if (zA) sm.s.list[0][baseA + __popc(balA & ((1u << lane) - 1u))] = tid;
        if (zB) sm.s.list[1][baseB + __popc(balB & ((1u << lane) - 1u))] = tid;
        nA = ntotA; nB = ntotB;
        __syncthreads();                       // (3) lists complete

        // ---- readout + exp filter: warp0 = batch A, warp1 = batch B ----
        if (warp < 2) {
            const int*   lst = sm.s.list[warp];
            const int    nn  = warp ? nB : nA;
            float y0 = 0.f, y1 = 0.f, y2 = 0.f, y3 = 0.f;
            int jj = 0;
            for (; jj + 3 < nn; jj += 4) {
                y0 += g_woutT[lst[jj]     * ODIM + lane];
                y1 += g_woutT[lst[jj + 1] * ODIM + lane];
                y2 += g_woutT[lst[jj + 2] * ODIM + lane];
                y3 += g_woutT[lst[jj + 3] * ODIM + lane];
            }
            for (; jj < nn; jj++)
                y0 += g_woutT[lst[jj] * ODIM + lane];
            float y = ((y0 + y1) + (y2 + y3)) + bo;
            if (warp == 0) {
                oA = (t == 0) ? y : oA + 0.2231435511314f * (y - oA);
                outA[(size_t)t * BATCH * ODIM + lane] = oA;
            } else {
                oB = (t == 0) ? y : oB + 0.2231435511314f * (y - oB);
                outB[(size_t)t * BATCH * ODIM + lane] = oB;
            }
        }

        icA = icA2;
        icB = icB2;
    }
}

// ---------------------------------------------------------------------------
extern "C" void kernel_launch(void* const* d_in, const int* in_sizes, int n_in,
                              void* d_out, int out_size) {
    const float* x     = (const float*)d_in[0];  // (T,B,F)
    const float* W_in  = (const float*)d_in[1];  // (H,F)
    const float* W_rec = (const float*)d_in[2];  // (H,H)
    const float* W_out = (const float*)d_in[3];  // (O,H)
    const float* b_out = (const float*)d_in[4];  // (O,)
    float* out = (float*)d_out;                  // (T,B,O)

    transpose_kernel<<<(HDIM * HDIM + 255) / 256, 256>>>(W_rec, W_out);

    // 64 SNN CTAs + 2000 GEMM producer CTAs, one launch, one stream
    fused_kernel<<<NSNN + (T_STEPS * BATCH / GBM) * (HDIM / GBN), 512>>>(
        x, W_in, b_out, out);
}

// round 5
// speedup vs baseline: 1.1681x; 1.1681x over previous
#include <cuda_runtime.h>
#include <math.h>

#define T_STEPS 500
#define BATCH   128
#define FDIM    128
#define HDIM    512
#define ODIM    32

#define NG  16     // batch groups
#define GSZ 8      // batches per group
#define NS  8      // H slices (CTAs per group)
#define DSTW 64    // dst neurons per slice

#define GBM 128
#define GBN 128
#define GBK 32

// Device-global scratch (sanctioned allocation-free path)
__device__ float g_iin[T_STEPS * BATCH * HDIM];          // x @ W_in^T
__device__ float g_wrecT[HDIM * HDIM];                   // W_rec^T [src][dst]
__device__ float g_woutT[HDIM * ODIM];                   // W_out^T [h][o]
__device__ unsigned long long g_zall[T_STEPS * NG * GSZ * NS];  // spike bitmasks
__device__ int   g_sync[T_STEPS * NG];                   // per-(t,group) barrier

// ---------------------------------------------------------------------------
// Transposes + zero per-replay sync counters
// ---------------------------------------------------------------------------
__global__ void transpose_kernel(const float* __restrict__ W_rec,
                                 const float* __restrict__ W_out) {
    int idx = blockIdx.x * blockDim.x + threadIdx.x;
    if (idx < HDIM * HDIM) {
        int r = idx / HDIM, c = idx % HDIM;
        g_wrecT[c * HDIM + r] = W_rec[idx];
    }
    if (idx < ODIM * HDIM) {
        int o = idx / HDIM, h = idx % HDIM;
        g_woutT[h * ODIM + o] = W_out[idx];
    }
    if (idx < T_STEPS * NG) g_sync[idx] = 0;
}

// ---------------------------------------------------------------------------
// GEMM: g_iin[m,n] = sum_k X[m,k] * W_in[n,k]   (verbatim from R2 — verified)
// ---------------------------------------------------------------------------
__global__ void __launch_bounds__(256) gemm_iin_kernel(
    const float* __restrict__ X, const float* __restrict__ Win) {
    __shared__ float As[GBK][GBM + 4];
    __shared__ float Bs[GBK][GBN + 4];

    const int tid = threadIdx.x;
    const int bm = blockIdx.y;
    const int bn = blockIdx.x;
    const float* Xb = X   + (size_t)bm * GBM * FDIM;
    const float* Wb = Win + (size_t)bn * GBN * FDIM;

    const int ty = tid >> 4;
    const int tx = tid & 15;
    const int lrow = tid >> 3;
    const int lcol = (tid & 7) * 4;

    float acc[8][8] = {};

    for (int k0 = 0; k0 < FDIM; k0 += GBK) {
        #pragma unroll
        for (int p = 0; p < 4; p++) {
            int r = lrow + p * 32;
            float4 va = *(const float4*)(Xb + (size_t)r * FDIM + k0 + lcol);
            As[lcol + 0][r] = va.x; As[lcol + 1][r] = va.y;
            As[lcol + 2][r] = va.z; As[lcol + 3][r] = va.w;
            float4 vb = *(const float4*)(Wb + (size_t)r * FDIM + k0 + lcol);
            Bs[lcol + 0][r] = vb.x; Bs[lcol + 1][r] = vb.y;
            Bs[lcol + 2][r] = vb.z; Bs[lcol + 3][r] = vb.w;
        }
        __syncthreads();

        #pragma unroll
        for (int k = 0; k < GBK; k++) {
            float af[8], bf[8];
            *(float4*)(af)     = *(const float4*)&As[k][ty * 8];
            *(float4*)(af + 4) = *(const float4*)&As[k][ty * 8 + 4];
            *(float4*)(bf)     = *(const float4*)&Bs[k][tx * 8];
            *(float4*)(bf + 4) = *(const float4*)&Bs[k][tx * 8 + 4];
            #pragma unroll
            for (int i = 0; i < 8; i++)
                #pragma unroll
                for (int j = 0; j < 8; j++)
                    acc[i][j] += af[i] * bf[j];
        }
        __syncthreads();
    }

    float* C = g_iin + (size_t)(bm * GBM) * HDIM + bn * GBN;
    #pragma unroll
    for (int i = 0; i < 8; i++) {
        float4 v0, v1;
        v0.x = acc[i][0]; v0.y = acc[i][1]; v0.z = acc[i][2]; v0.w = acc[i][3];
        v1.x = acc[i][4]; v1.y = acc[i][5]; v1.z = acc[i][6]; v1.w = acc[i][7];
        float* Crow = C + (size_t)(ty * 8 + i) * HDIM + tx * 8;
        *(float4*)(Crow)     = v0;
        *(float4*)(Crow + 4) = v1;
    }
}

// ---------------------------------------------------------------------------
// SNN kernel: CTA = (group g of 8 batches, dst slice s of 64 neurons).
// W_recT slice (512x64 fp32 = 128 KB) cached in SMEM; gathers hit SMEM only.
// Per-step cross-slice spike exchange via global bitmasks + atomic barrier.
// Thread layout: warp w -> batch b = w>>1, dst d = (w&1)*32 + lane.
// ---------------------------------------------------------------------------
__global__ void __launch_bounds__(512, 1) snn_kernel() {
    extern __shared__ char sh[];
    float*              w_s    = (float*)sh;                         // 131072 B
    int*                s_list = (int*)(sh + 131072);                // 16384 B
    unsigned long long* s_mask = (unsigned long long*)(sh + 147456); // 512 B
    int*                s_cnt  = (int*)(sh + 147968);                // 256 B
    unsigned*           s_half = (unsigned*)(sh + 148224);           // 64 B
    int*                s_n    = (int*)(sh + 148288);                // 32 B

    const int g    = blockIdx.x >> 3;
    const int s    = blockIdx.x & 7;
    const int tid  = threadIdx.x;
    const int warp = tid >> 5;
    const int lane = tid & 31;
    const int b    = warp >> 1;                 // local batch 0..7
    const int d    = ((warp & 1) << 5) + lane;  // dst 0..63

    // stage W_recT slice: w_s[h][d] = g_wrecT[h][s*64+d]
    for (int idx = tid; idx < HDIM * DSTW; idx += 512)
        w_s[idx] = g_wrecT[((idx >> 6) << 9) + (s << 6) + (idx & 63)];
    if (tid < 64) { s_mask[tid] = 0ull; s_cnt[tid] = 0; }
    if (tid < 8)  s_n[tid] = 0;
    __syncthreads();

    const int gb = (g << 3) + b;                // global batch
    float v = 0.f, ii = 0.f, aa = 0.f;
    const float* iin = g_iin + (size_t)gb * HDIM + (s << 6) + d;
    const char*  wp  = (const char*)w_s + ((size_t)d << 2);
    const int*   lp  = s_list + (b << 9);

    for (int t = 0; t < T_STEPS; t++) {
        float ic = __ldg(iin + (size_t)t * (BATCH * HDIM));

        // ---- SMEM gather over the precomputed offset list of batch b ----
        const int nb = s_n[b];
        float a0 = 0.f, a1 = 0.f, a2 = 0.f, a3 = 0.f;
        int j = 0;
        for (; j + 4 <= nb; j += 4) {
            int4 o = *(const int4*)(lp + j);
            a0 += *(const float*)(wp + o.x);
            a1 += *(const float*)(wp + o.y);
            a2 += *(const float*)(wp + o.z);
            a3 += *(const float*)(wp + o.w);
        }
        for (; j < nb; j++)
            a0 += *(const float*)(wp + lp[j]);
        float rec = ((a0 + a1) + (a2 + a3));

        // ---- LIF-AdEx update (grouping mirrors the JAX reference) ----
        float dv   = 0.1f * ((((0.f - v) + 0.5f * expf((v - 1.f) * 2.f)) + ii) - aa);
        float vdec = v + dv;
        float idec = ii - 0.2f * ii;
        float adec = aa + 0.002f * (4.f * v - aa);
        int   z    = (vdec - 1.f) > 0.f;
        v  = z ? 0.f : vdec;
        ii = (idec + ic) + rec;
        aa = adec + (z ? 0.02f : 0.f);

        // ---- pack local 64-dst spike bits ----
        unsigned bal = __ballot_sync(0xffffffffu, z);
        if (lane == 0) s_half[warp] = bal;
        __syncthreads();
        if (tid < 8) {
            unsigned long long m64 =
                (unsigned long long)s_half[tid << 1] |
                ((unsigned long long)s_half[(tid << 1) + 1] << 32);
            g_zall[(((size_t)t * NG + g) * GSZ + tid) * NS + s] = m64;
            __threadfence();
        }
        __syncthreads();                 // publishes + fences done

        // ---- group barrier (8 slice-CTAs, all co-resident) ----
        if (tid == 0) {
            atomicAdd(&g_sync[t * NG + g], 1);
            volatile int* p = &g_sync[t * NG + g];
            while (*p < NS) __nanosleep(40);
        }
        __syncthreads();

        // ---- fetch merged masks (L2, lines are first-touch per t) ----
        if (tid < 64)
            s_mask[tid] = __ldcg(&g_zall[(((size_t)t * NG + g) * GSZ + (tid >> 3)) * NS + (tid & 7)]);
        __syncthreads();
        if (tid < 64) s_cnt[tid] = __popcll(s_mask[tid]);
        __syncthreads();

        // ---- expand masks to per-batch byte-offset lists ----
        if (tid < 64) {
            int bb = tid >> 3, w8 = tid & 7;
            int base = 0;
            #pragma unroll
            for (int q = 0; q < 7; q++)
                if (q < w8) base += s_cnt[(bb << 3) + q];
            unsigned long long m = s_mask[tid];
            int* out_l = s_list + (bb << 9) + base;
            int off0 = w8 << 14;                  // (w8*64) rows * 256 B
            while (m) {
                int bit = __ffsll(m) - 1;
                m &= m - 1;
                *out_l++ = off0 + (bit << 8);     // row h -> h*256 bytes
            }
            if (w8 == 7) s_n[bb] = base + s_cnt[tid];
        }
        __syncthreads();
    }
}

// ---------------------------------------------------------------------------
// Readout: one CTA per batch. Phase 1: warps compute y[t] from spike masks
// (strided over t). Phase 2: warp 0 runs the serial IIR filter.
// ---------------------------------------------------------------------------
__global__ void __launch_bounds__(512) readout_kernel(
    const float* __restrict__ b_out, float* __restrict__ out) {
    extern __shared__ float y_buf[];            // [T_STEPS][ODIM] = 64000 B
    const int B    = blockIdx.x;
    const int tid  = threadIdx.x;
    const int warp = tid >> 5;
    const int lane = tid & 31;
    const int g    = B >> 3;
    const int bb   = B & 7;

    float bo = b_out[lane];

    for (int t = warp; t < T_STEPS; t += 16) {
        const unsigned long long* mp =
            g_zall + (((size_t)t * NG + g) * GSZ + bb) * NS;
        float y0 = 0.f, y1 = 0.f;
        #pragma unroll
        for (int w8 = 0; w8 < 8; w8++) {
            unsigned long long m = __ldg(mp + w8);
            const float* wop = g_woutT + (w8 << 11) + lane;
            while (m) {
                int bit = __ffsll(m) - 1;
                m &= m - 1;
                y0 += wop[bit << 5];
                if (!m) break;
                int bit2 = __ffsll(m) - 1;
                m &= m - 1;
                y1 += wop[bit2 << 5];
            }
        }
        y_buf[t * ODIM + lane] = (y0 + y1) + bo;
    }
    __syncthreads();

    if (warp == 0) {
        float o = y_buf[lane];                   // o0 = y[0]
        out[(size_t)B * ODIM + lane] = o;
        for (int t = 1; t < T_STEPS; t++) {
            float y = y_buf[t * ODIM + lane];
            o = o + 0.2231435511314f * (y - o);
            out[((size_t)t * BATCH + B) * ODIM + lane] = o;
        }
    }
}

// ---------------------------------------------------------------------------
extern "C" void kernel_launch(void* const* d_in, const int* in_sizes, int n_in,
                              void* d_out, int out_size) {
    const float* x     = (const float*)d_in[0];  // (T,B,F)
    const float* W_in  = (const float*)d_in[1];  // (H,F)
    const float* W_rec = (const float*)d_in[2];  // (H,H)
    const float* W_out = (const float*)d_in[3];  // (O,H)
    const float* b_out = (const float*)d_in[4];  // (O,)
    float* out = (float*)d_out;                  // (T,B,O)

    static const int SNN_SMEM  = 148352;
    static const int RDO_SMEM  = T_STEPS * ODIM * (int)sizeof(float);
    cudaFuncSetAttribute(snn_kernel,
                         cudaFuncAttributeMaxDynamicSharedMemorySize, SNN_SMEM);
    cudaFuncSetAttribute(readout_kernel,
                         cudaFuncAttributeMaxDynamicSharedMemorySize, RDO_SMEM);

    transpose_kernel<<<(HDIM * HDIM + 255) / 256, 256>>>(W_rec, W_out);

    dim3 ggrid(HDIM / GBN, (T_STEPS * BATCH) / GBM);  // (4, 500)
    gemm_iin_kernel<<<ggrid, 256>>>(x, W_in);

    snn_kernel<<<NG * NS, 512, SNN_SMEM>>>();

    readout_kernel<<<BATCH, 512, RDO_SMEM>>>(b_out, out);
}